// round 7
// baseline (speedup 1.0000x reference)
#include <cuda_runtime.h>
#include <math.h>
#include <stdint.h>

#define Bb   8
#define Nn   2048
#define FIN  256
#define FOUT 128
#define CH   32          // j-chunk
#define NCH  (Nn / CH)   // 64

typedef unsigned long long u64;
typedef unsigned int u32;

// Scratch (device globals: allocation-free rule)
__device__ float g_WhT[Bb * FOUT * Nn];    // [b][f][j], tf32-rounded bits
__device__ float g_Ei[Bb * Nn];            // exp(f1) per i-node
__device__ float g_Ej[Bb * Nn];            // exp(f2) per j-node

// ---------------- helpers ----------------
__forceinline__ __device__ u64 pk2(float lo, float hi) {
    u64 r; asm("mov.b64 %0,{%1,%2};" : "=l"(r) : "f"(lo), "f"(hi)); return r;
}
__forceinline__ __device__ void upk2(u64 v, float &lo, float &hi) {
    asm("mov.b64 {%0,%1},%2;" : "=f"(lo), "=f"(hi) : "l"(v));
}
__forceinline__ __device__ void fma2(u64 &d, u64 a, u64 b) {
    asm("fma.rn.f32x2 %0,%1,%2,%3;" : "=l"(d) : "l"(a), "l"(b), "l"(d));
}
__forceinline__ __device__ u32 tf32r(float f) {
    u32 r; asm("cvt.rna.tf32.f32 %0,%1;" : "=r"(r) : "f"(f)); return r;
}
__forceinline__ __device__ u32 smem_u32(const void* p) {
    u32 a;
    asm("{ .reg .u64 t; cvta.to.shared.u64 t,%1; cvt.u32.u64 %0,t; }" : "=r"(a) : "l"(p));
    return a;
}
// m16n8k8 tf32 MMA (legacy tensor path; compute_80+ feature)
__forceinline__ __device__ void mma168(float* d, const u32* a, const u32* b) {
    asm volatile(
        "mma.sync.aligned.m16n8k8.row.col.f32.tf32.tf32.f32 "
        "{%0,%1,%2,%3},{%4,%5,%6,%7},{%8,%9},{%0,%1,%2,%3};"
        : "+f"(d[0]), "+f"(d[1]), "+f"(d[2]), "+f"(d[3])
        : "r"(a[0]), "r"(a[1]), "r"(a[2]), "r"(a[3]), "r"(b[0]), "r"(b[1]));
}
// ldmatrix x4: four 8x8 b16 matrices == tf32 fragment quads over f32 data
__forceinline__ __device__ void ldmx4(u32* d, u32 addr) {
    asm volatile("ldmatrix.sync.aligned.m8n8.x4.shared.b16 {%0,%1,%2,%3},[%4];"
        : "=r"(d[0]), "=r"(d[1]), "=r"(d[2]), "=r"(d[3]) : "r"(addr));
}
#define CP_ASYNC16(sdst, gsrc) \
    asm volatile("cp.async.cg.shared.global [%0], [%1], 16;" :: "r"(sdst), "l"(gsrc))
#define CP_COMMIT()  asm volatile("cp.async.commit_group;" ::: "memory")
#define CP_WAIT0()   asm volatile("cp.async.wait_group 0;" ::: "memory")

// ============================================================
// Kernel 1: Wh = x@W (fp32 scalar, BM=64), fused epilogue:
//   exp(f1)/exp(f2) per row -> g_Ei/g_Ej,
//   WhT[b][f][j] (tf32-rounded) via smem transpose.
// ============================================================
__global__ __launch_bounds__(256) void gat_gemm_wh(
    const float* __restrict__ x, const float* __restrict__ W,
    const float* __restrict__ a)
{
    __shared__ __align__(16) char arena[64 * 129 * 4 + 64];   // 33 KB (aliased)
    __shared__ float a_s[2 * FOUT];
    float (*xs)[32]    = (float(*)[32])arena;                 // 64x32 (8 KB)
    float (*ws)[FOUT]  = (float(*)[FOUT])(arena + 8192);      // 32x128 (16 KB)
    float (*trans)[129] = (float(*)[129])arena;               // 64x129 (reuse)

    const int t  = threadIdx.x;
    const int b  = blockIdx.y;
    const int i0 = blockIdx.x * 64;
    const int tr = t >> 4, tc = t & 15;
    const int r0 = tr * 4, c0a = tc * 4, c0b = 64 + tc * 4;

    a_s[t] = a[t];

    u64 acc[4][4];
    #pragma unroll
    for (int i = 0; i < 4; i++)
        #pragma unroll
        for (int j = 0; j < 4; j++) acc[i][j] = pk2(0.f, 0.f);

    const float* xb = x + ((size_t)b * Nn + i0) * FIN;

    float4 rx[2], rw[4];
    #pragma unroll
    for (int v = 0; v < 2; v++) {
        int flat = t + 256 * v;
        rx[v] = *(const float4*)&xb[(size_t)(flat >> 3) * FIN + (flat & 7) * 4];
    }
    #pragma unroll
    for (int v = 0; v < 4; v++) {
        int flat = t + 256 * v;
        rw[v] = *(const float4*)&W[(size_t)(flat >> 5) * FOUT + (flat & 31) * 4];
    }

    for (int kt = 0; kt < 8; kt++) {
        if (kt > 0) __syncthreads();
        #pragma unroll
        for (int v = 0; v < 2; v++) {
            int flat = t + 256 * v;
            *(float4*)&xs[flat >> 3][(flat & 7) * 4] = rx[v];
        }
        #pragma unroll
        for (int v = 0; v < 4; v++) {
            int flat = t + 256 * v;
            *(float4*)&ws[flat >> 5][(flat & 31) * 4] = rw[v];
        }
        __syncthreads();
        if (kt < 7) {
            int k0 = (kt + 1) * 32;
            #pragma unroll
            for (int v = 0; v < 2; v++) {
                int flat = t + 256 * v;
                rx[v] = *(const float4*)&xb[(size_t)(flat >> 3) * FIN + k0 + (flat & 7) * 4];
            }
            #pragma unroll
            for (int v = 0; v < 4; v++) {
                int flat = t + 256 * v;
                rw[v] = *(const float4*)&W[(size_t)(k0 + (flat >> 5)) * FOUT + (flat & 31) * 4];
            }
        }
        #pragma unroll
        for (int kk = 0; kk < 32; kk++) {
            const u64* wrow = (const u64*)&ws[kk][0];
            u64 w0 = wrow[tc * 2], w1 = wrow[tc * 2 + 1];
            u64 w2 = wrow[32 + tc * 2], w3 = wrow[32 + tc * 2 + 1];
            #pragma unroll
            for (int ri = 0; ri < 4; ri++) {
                float av = xs[r0 + ri][kk];
                u64 ap = pk2(av, av);
                fma2(acc[ri][0], ap, w0);
                fma2(acc[ri][1], ap, w1);
                fma2(acc[ri][2], ap, w2);
                fma2(acc[ri][3], ap, w3);
            }
        }
    }

    float v[4][8];
    #pragma unroll
    for (int ri = 0; ri < 4; ri++) {
        upk2(acc[ri][0], v[ri][0], v[ri][1]); upk2(acc[ri][1], v[ri][2], v[ri][3]);
        upk2(acc[ri][2], v[ri][4], v[ri][5]); upk2(acc[ri][3], v[ri][6], v[ri][7]);
    }

    __syncthreads();   // done with xs/ws; arena becomes trans

    #pragma unroll
    for (int ri = 0; ri < 4; ri++) {
        float p1 = 0.f, p2 = 0.f;
        #pragma unroll
        for (int u = 0; u < 4; u++) {
            p1 += v[ri][u] * a_s[c0a + u] + v[ri][4 + u] * a_s[c0b + u];
            p2 += v[ri][u] * a_s[FOUT + c0a + u] + v[ri][4 + u] * a_s[FOUT + c0b + u];
        }
        #pragma unroll
        for (int o = 8; o > 0; o >>= 1) {
            p1 += __shfl_xor_sync(0xffffffffu, p1, o);
            p2 += __shfl_xor_sync(0xffffffffu, p2, o);
        }
        if (tc == 0) {
            size_t row = (size_t)b * Nn + i0 + r0 + ri;
            g_Ei[row] = __expf(p1);
            g_Ej[row] = __expf(p2);
        }
        #pragma unroll
        for (int u = 0; u < 4; u++) {
            trans[r0 + ri][c0a + u] = v[ri][u];
            trans[r0 + ri][c0b + u] = v[ri][4 + u];
        }
    }
    __syncthreads();

    const int f  = t >> 1;
    const int jp = t & 1;
    float* wtrow = g_WhT + ((size_t)(b * FOUT + f)) * Nn + i0 + jp * 32;
    #pragma unroll
    for (int q = 0; q < 8; q++) {
        uint4 pv;
        pv.x = tf32r(trans[jp * 32 + q * 4 + 0][f]);
        pv.y = tf32r(trans[jp * 32 + q * 4 + 1][f]);
        pv.z = tf32r(trans[jp * 32 + q * 4 + 2][f]);
        pv.w = tf32r(trans[jp * 32 + q * 4 + 3][f]);
        *(uint4*)&wtrow[q * 4] = pv;
    }
}

// ============================================================
// Kernel 2: fused attention, mma.sync m16n8k8 tf32.
// CTA: 32 i x 128 f (grid 512, ~3.5 CTAs/SM, occ 3).
// 8 warps: wr=wid&1 (16-row half), wc=wid>>1 (32 f).
// Builder: p from exp factors only (E2 + per-row c1), no jpack smem.
// ============================================================
#define SM_PS   0                        // 2 * 32*32*4   = 8192
#define SM_WS   8192                     // 2 * 128*32*4  = 32768
#define SM_RS   40960                    // 32 floats
#define SM_TOT  41216

__global__ __launch_bounds__(256, 3) void gat_attn(
    const int* __restrict__ adj, float* __restrict__ out)
{
    extern __shared__ __align__(16) char dsm[];
    u32*   Ps   = (u32*)(dsm + SM_PS);
    float* rows = (float*)(dsm + SM_RS);
    const u32 sb = smem_u32(dsm);

    const int t    = threadIdx.x;
    const int lane = t & 31;
    const int wid  = t >> 5;
    const int wr   = wid & 1;
    const int wc   = wid >> 1;
    const int g    = lane >> 2;
    const int cl   = lane & 3;
    const int b    = blockIdx.y;
    const int i0   = blockIdx.x * 32;

    // ldmatrix row-offset precompute (bytes from buffer base)
    const int sel = lane >> 3, rin = lane & 7;
    u32 a_off[4], b_off[4][2];
    #pragma unroll
    for (int ks = 0; ks < 4; ks++) {
        int r  = wr * 16 + ((sel & 1) << 3) + rin;
        int cg = ks * 2 + (sel >> 1);
        a_off[ks] = (u32)(r * 128 + ((u32)(cg ^ (r & 7)) << 4));
    }
    #pragma unroll
    for (int nt = 0; nt < 4; nt++)
        #pragma unroll
        for (int kp = 0; kp < 2; kp++) {
            int rr = wc * 32 + nt * 8 + rin;
            int cg = (kp * 2 + (sel >> 1)) * 2 + (sel & 1);
            b_off[nt][kp] = (u32)(rr * 128 + ((u32)(cg ^ (rr & 7)) << 4));
        }

    // builder mapping: row iL = t>>3, 4 j's at jh
    const int iL = t >> 3;
    const int jh = (t & 7) * 4;
    const u32 psw = ((u32)(iL & 7)) << 2;

    const float c1   = g_Ei[(size_t)b * Nn + i0 + iL];
    const float c2   = c1 * c1;
    const float thrE = 1.0f / c1;
    const int*   arow = adj  + ((size_t)(b * Nn + i0 + iL)) * Nn + jh;
    const float* Ejb  = g_Ej + (size_t)b * Nn + jh;
    const float* whtb = g_WhT + (size_t)b * FOUT * Nn;

    float acc[4][4];
    #pragma unroll
    for (int nt = 0; nt < 4; nt++)
        #pragma unroll
        for (int e = 0; e < 4; e++) acc[nt][e] = 0.f;

    int4   sav;
    float4 sev;
    float  rs = 0.f;

    #define ISSUE_G(c_) do {                                             \
        const int _j0 = (c_) * CH;                                       \
        sav = *(const int4*)&arow[_j0];                                  \
        sev = *(const float4*)&Ejb[_j0];                                 \
    } while (0)

    #define ISSUE_W(c_, buf_) do {                                       \
        const int _j0 = (c_) * CH;                                       \
        const u32 _wb = sb + SM_WS + (buf_) * 16384;                     \
        _Pragma("unroll")                                                \
        for (int q = 0; q < 4; q++) {                                    \
            int flat = t + 256 * q;                                      \
            int row  = flat >> 3;                                        \
            int jq   = (flat & 7) * 4;                                   \
            u32 sidx = (u32)(row * 32) + ((u32)jq ^ (((u32)(row & 7)) << 2)); \
            CP_ASYNC16(_wb + (sidx << 2),                                \
                       &whtb[(size_t)row * Nn + _j0 + jq]);              \
        }                                                                 \
        CP_COMMIT();                                                      \
    } while (0)

    #define FINISH(buf_) do {                                             \
        u32* _P = Ps + (buf_) * 1024;                                     \
        const int*   _a = (const int*)&sav;                               \
        const float* _e = (const float*)&sev;                             \
        uint4 pv; u32* pw = (u32*)&pv;                                    \
        _Pragma("unroll")                                                 \
        for (int u = 0; u < 4; u++) {                                     \
            float E2 = _e[u];                                             \
            float m  = (E2 >= thrE) ? c1 : c2 * E2;                       \
            float p  = m * E2;                                            \
            p = (_a[u] > 0) ? p : 0.f;                                    \
            pw[u] = tf32r(p);                                             \
            rs += __uint_as_float(pw[u]);                                 \
        }                                                                  \
        *(uint4*)&_P[iL * 32 + ((u32)jh ^ psw)] = pv;                     \
    } while (0)

    // prologue: chunk 0 (builder needs only regs -> no staging barrier)
    ISSUE_W(0, 0);
    ISSUE_G(0);
    FINISH(0);
    CP_WAIT0();
    __syncthreads();

    for (int c = 0; c < NCH; c++) {
        const int s = c & 1;
        if (c < NCH - 1) { ISSUE_G(c + 1); ISSUE_W(c + 1, s ^ 1); }

        // MMA on buffer s
        {
            const u32 pb = sb + SM_PS + s * 4096;
            const u32 wb = sb + SM_WS + s * 16384;
            #pragma unroll
            for (int kp = 0; kp < 2; kp++) {
                u32 bfr[4][4];
                #pragma unroll
                for (int nt = 0; nt < 4; nt++)
                    ldmx4(bfr[nt], wb + b_off[nt][kp]);
                #pragma unroll
                for (int h = 0; h < 2; h++) {
                    u32 afr[4];
                    ldmx4(afr, pb + a_off[kp * 2 + h]);
                    #pragma unroll
                    for (int nt = 0; nt < 4; nt++)
                        mma168(acc[nt], afr, &bfr[nt][h * 2]);
                }
            }
        }

        if (c < NCH - 1) FINISH(s ^ 1);
        CP_WAIT0();
        __syncthreads();
    }

    // rowsum: threads t..t|7 share builder row iL
    rs += __shfl_xor_sync(0xffffffffu, rs, 1);
    rs += __shfl_xor_sync(0xffffffffu, rs, 2);
    rs += __shfl_xor_sync(0xffffffffu, rs, 4);
    if ((t & 7) == 0) rows[iL] = rs;
    __syncthreads();

    // epilogue
    #pragma unroll
    for (int h = 0; h < 2; h++) {
        const int row = wr * 16 + g + h * 8;
        const float inv = 1.0f / rows[row];
        float* orow = out + ((size_t)(b * Nn + i0 + row)) * FOUT + wc * 32 + cl * 2;
        #pragma unroll
        for (int nt = 0; nt < 4; nt++) {
            float h0 = acc[nt][h * 2 + 0] * inv;
            float h1 = acc[nt][h * 2 + 1] * inv;
            h0 = (h0 > 0.f) ? h0 : expm1f(h0);
            h1 = (h1 > 0.f) ? h1 : expm1f(h1);
            float2 o = make_float2(h0, h1);
            *(float2*)&orow[nt * 8] = o;
        }
    }
}

// ============================================================
extern "C" void kernel_launch(void* const* d_in, const int* in_sizes, int n_in,
                              void* d_out, int out_size)
{
    const float* x   = (const float*)d_in[0];   // [8,2048,256] f32
    const int*   adj = (const int*)  d_in[1];   // [8,2048,2048] i32
    const float* W   = (const float*)d_in[2];   // [256,128] f32
    const float* a   = (const float*)d_in[3];   // [256,1] f32
    float*       out = (float*)d_out;           // [8,2048,128] f32

    dim3 g1(Nn / 64, Bb);
    gat_gemm_wh<<<g1, 256>>>(x, W, a);

    dim3 g2(Nn / 32, Bb);
    gat_attn<<<g2, 256, SM_TOT>>>(adj, out);
}

// round 8
// speedup vs baseline: 1.5018x; 1.5018x over previous
#include <cuda_runtime.h>
#include <cuda_fp16.h>
#include <math.h>
#include <stdint.h>

#define Bb   8
#define Nn   2048
#define FIN  256
#define FOUT 128
#define CH   64          // j-chunk (128-byte fp16 rows)
#define NCH  (Nn / CH)   // 32

typedef unsigned long long u64;
typedef unsigned int u32;

// Scratch (device globals: allocation-free rule)
__device__ __half g_WhT[Bb * FOUT * Nn];   // [b][f][j], fp16
__device__ float  g_Ei[Bb * Nn];           // exp(f1) per i-node
__device__ float  g_Ej[Bb * Nn];           // exp(f2) per j-node
__device__ float  g_maxE2[Bb];             // per-batch max of g_Ej

// ---------------- helpers ----------------
__forceinline__ __device__ u64 pk2(float lo, float hi) {
    u64 r; asm("mov.b64 %0,{%1,%2};" : "=l"(r) : "f"(lo), "f"(hi)); return r;
}
__forceinline__ __device__ void upk2(u64 v, float &lo, float &hi) {
    asm("mov.b64 {%0,%1},%2;" : "=f"(lo), "=f"(hi) : "l"(v));
}
__forceinline__ __device__ void fma2(u64 &d, u64 a, u64 b) {
    asm("fma.rn.f32x2 %0,%1,%2,%3;" : "=l"(d) : "l"(a), "l"(b), "l"(d));
}
__forceinline__ __device__ u32 pkh2(float lo, float hi) {   // lo -> low half
    u32 r; asm("cvt.rn.f16x2.f32 %0,%1,%2;" : "=r"(r) : "f"(hi), "f"(lo)); return r;
}
__forceinline__ __device__ u32 smem_u32(const void* p) {
    u32 a;
    asm("{ .reg .u64 t; cvta.to.shared.u64 t,%1; cvt.u32.u64 %0,t; }" : "=r"(a) : "l"(p));
    return a;
}
// m16n8k16 fp16 MMA, fp32 accum (legacy tensor path; compute_80+)
__forceinline__ __device__ void mma16816(float* d, const u32* a, const u32* b) {
    asm volatile(
        "mma.sync.aligned.m16n8k16.row.col.f32.f16.f16.f32 "
        "{%0,%1,%2,%3},{%4,%5,%6,%7},{%8,%9},{%0,%1,%2,%3};"
        : "+f"(d[0]), "+f"(d[1]), "+f"(d[2]), "+f"(d[3])
        : "r"(a[0]), "r"(a[1]), "r"(a[2]), "r"(a[3]), "r"(b[0]), "r"(b[1]));
}
__forceinline__ __device__ void ldmx4(u32* d, u32 addr) {
    asm volatile("ldmatrix.sync.aligned.m8n8.x4.shared.b16 {%0,%1,%2,%3},[%4];"
        : "=r"(d[0]), "=r"(d[1]), "=r"(d[2]), "=r"(d[3]) : "r"(addr));
}
#define CP_ASYNC16(sdst, gsrc) \
    asm volatile("cp.async.cg.shared.global [%0], [%1], 16;" :: "r"(sdst), "l"(gsrc))
#define CP_COMMIT()  asm volatile("cp.async.commit_group;" ::: "memory")
#define CP_WAIT0()   asm volatile("cp.async.wait_group 0;" ::: "memory")

// ============================================================
// Kernel 1: Wh = x@W (fp32 scalar, BM=64), fused epilogue:
//   exp(f1)/exp(f2) -> g_Ei/g_Ej, WhT fp16 via smem transpose.
// ============================================================
__global__ __launch_bounds__(256) void gat_gemm_wh(
    const float* __restrict__ x, const float* __restrict__ W,
    const float* __restrict__ a)
{
    __shared__ __align__(16) char arena[64 * 129 * 4 + 64];
    __shared__ float a_s[2 * FOUT];
    float (*xs)[32]    = (float(*)[32])arena;
    float (*ws)[FOUT]  = (float(*)[FOUT])(arena + 8192);
    float (*trans)[129] = (float(*)[129])arena;

    const int t  = threadIdx.x;
    const int b  = blockIdx.y;
    const int i0 = blockIdx.x * 64;
    const int tr = t >> 4, tc = t & 15;
    const int r0 = tr * 4, c0a = tc * 4, c0b = 64 + tc * 4;

    a_s[t] = a[t];

    u64 acc[4][4];
    #pragma unroll
    for (int i = 0; i < 4; i++)
        #pragma unroll
        for (int j = 0; j < 4; j++) acc[i][j] = pk2(0.f, 0.f);

    const float* xb = x + ((size_t)b * Nn + i0) * FIN;

    float4 rx[2], rw[4];
    #pragma unroll
    for (int v = 0; v < 2; v++) {
        int flat = t + 256 * v;
        rx[v] = *(const float4*)&xb[(size_t)(flat >> 3) * FIN + (flat & 7) * 4];
    }
    #pragma unroll
    for (int v = 0; v < 4; v++) {
        int flat = t + 256 * v;
        rw[v] = *(const float4*)&W[(size_t)(flat >> 5) * FOUT + (flat & 31) * 4];
    }

    for (int kt = 0; kt < 8; kt++) {
        if (kt > 0) __syncthreads();
        #pragma unroll
        for (int v = 0; v < 2; v++) {
            int flat = t + 256 * v;
            *(float4*)&xs[flat >> 3][(flat & 7) * 4] = rx[v];
        }
        #pragma unroll
        for (int v = 0; v < 4; v++) {
            int flat = t + 256 * v;
            *(float4*)&ws[flat >> 5][(flat & 31) * 4] = rw[v];
        }
        __syncthreads();
        if (kt < 7) {
            int k0 = (kt + 1) * 32;
            #pragma unroll
            for (int v = 0; v < 2; v++) {
                int flat = t + 256 * v;
                rx[v] = *(const float4*)&xb[(size_t)(flat >> 3) * FIN + k0 + (flat & 7) * 4];
            }
            #pragma unroll
            for (int v = 0; v < 4; v++) {
                int flat = t + 256 * v;
                rw[v] = *(const float4*)&W[(size_t)(k0 + (flat >> 5)) * FOUT + (flat & 31) * 4];
            }
        }
        #pragma unroll
        for (int kk = 0; kk < 32; kk++) {
            const u64* wrow = (const u64*)&ws[kk][0];
            u64 w0 = wrow[tc * 2], w1 = wrow[tc * 2 + 1];
            u64 w2 = wrow[32 + tc * 2], w3 = wrow[32 + tc * 2 + 1];
            #pragma unroll
            for (int ri = 0; ri < 4; ri++) {
                float av = xs[r0 + ri][kk];
                u64 ap = pk2(av, av);
                fma2(acc[ri][0], ap, w0);
                fma2(acc[ri][1], ap, w1);
                fma2(acc[ri][2], ap, w2);
                fma2(acc[ri][3], ap, w3);
            }
        }
    }

    float v[4][8];
    #pragma unroll
    for (int ri = 0; ri < 4; ri++) {
        upk2(acc[ri][0], v[ri][0], v[ri][1]); upk2(acc[ri][1], v[ri][2], v[ri][3]);
        upk2(acc[ri][2], v[ri][4], v[ri][5]); upk2(acc[ri][3], v[ri][6], v[ri][7]);
    }

    __syncthreads();   // arena becomes trans

    #pragma unroll
    for (int ri = 0; ri < 4; ri++) {
        float p1 = 0.f, p2 = 0.f;
        #pragma unroll
        for (int u = 0; u < 4; u++) {
            p1 += v[ri][u] * a_s[c0a + u] + v[ri][4 + u] * a_s[c0b + u];
            p2 += v[ri][u] * a_s[FOUT + c0a + u] + v[ri][4 + u] * a_s[FOUT + c0b + u];
        }
        #pragma unroll
        for (int o = 8; o > 0; o >>= 1) {
            p1 += __shfl_xor_sync(0xffffffffu, p1, o);
            p2 += __shfl_xor_sync(0xffffffffu, p2, o);
        }
        if (tc == 0) {
            size_t row = (size_t)b * Nn + i0 + r0 + ri;
            g_Ei[row] = __expf(p1);
            g_Ej[row] = __expf(p2);
        }
        #pragma unroll
        for (int u = 0; u < 4; u++) {
            trans[r0 + ri][c0a + u] = v[ri][u];
            trans[r0 + ri][c0b + u] = v[ri][4 + u];
        }
    }
    __syncthreads();

    // write WhT fp16 (coalesced: thread -> f = t>>1, 32 j halves)
    const int f  = t >> 1;
    const int jp = t & 1;
    __half* wtrow = g_WhT + ((size_t)(b * FOUT + f)) * Nn + i0 + jp * 32;
    #pragma unroll
    for (int q = 0; q < 4; q++) {
        uint4 pv;
        pv.x = pkh2(trans[jp * 32 + q * 8 + 0][f], trans[jp * 32 + q * 8 + 1][f]);
        pv.y = pkh2(trans[jp * 32 + q * 8 + 2][f], trans[jp * 32 + q * 8 + 3][f]);
        pv.z = pkh2(trans[jp * 32 + q * 8 + 4][f], trans[jp * 32 + q * 8 + 5][f]);
        pv.w = pkh2(trans[jp * 32 + q * 8 + 6][f], trans[jp * 32 + q * 8 + 7][f]);
        *(uint4*)&wtrow[q * 8] = pv;
    }
}

// ============================================================
// Kernel 1b: per-batch max of g_Ej (for fp16 range scaling)
// ============================================================
__global__ __launch_bounds__(256) void gat_maxe()
{
    const int b = blockIdx.x;
    const int t = threadIdx.x;
    float m = 0.f;
    #pragma unroll
    for (int q = 0; q < 8; q++)
        m = fmaxf(m, g_Ej[(size_t)b * Nn + t + 256 * q]);
    #pragma unroll
    for (int o = 16; o > 0; o >>= 1)
        m = fmaxf(m, __shfl_xor_sync(0xffffffffu, m, o));
    __shared__ float sm[8];
    if ((t & 31) == 0) sm[t >> 5] = m;
    __syncthreads();
    if (t == 0) {
        float r = sm[0];
        #pragma unroll
        for (int w = 1; w < 8; w++) r = fmaxf(r, sm[w]);
        g_maxE2[b] = r;
    }
}

// ============================================================
// Kernel 2: fused attention, mma.sync m16n8k16 fp16 (fp32 accum).
// CTA: 32 i x 128 f (grid 512). j chunks of 64, double-buffered.
// P scaled per-row by power-of-2 (cancels in softmax) for fp16 range.
// ============================================================
#define SM_PS   0                        // 2 * 32*128B  = 8192
#define SM_WS   8192                     // 2 * 128*128B = 32768
#define SM_RS   40960                    // 32 floats
#define SM_TOT  41216

__global__ __launch_bounds__(256, 3) void gat_attn(
    const int* __restrict__ adj, float* __restrict__ out)
{
    extern __shared__ __align__(16) char dsm[];
    float* rows = (float*)(dsm + SM_RS);
    const u32 sb = smem_u32(dsm);

    const int t    = threadIdx.x;
    const int lane = t & 31;
    const int wid  = t >> 5;
    const int wr   = wid & 1;           // 16-row half
    const int wc   = wid >> 1;          // 32-col group
    const int g    = lane >> 2;
    const int cl   = lane & 3;
    const int b    = blockIdx.y;
    const int i0   = blockIdx.x * 32;

    // ldmatrix byte offsets (128-B rows, 16B-chunk XOR swizzle)
    const int sel = lane >> 3, rin = lane & 7;
    u32 a_off[4], b_off[4][2];
    #pragma unroll
    for (int ks = 0; ks < 4; ks++) {        // k-step of 16 halves = 2 chunks
        int r = wr * 16 + ((sel & 1) << 3) + rin;
        int c = ks * 2 + (sel >> 1);
        a_off[ks] = (u32)(r * 128 + ((u32)(c ^ (r & 7)) << 4));
    }
    #pragma unroll
    for (int nt = 0; nt < 4; nt++)
        #pragma unroll
        for (int kb = 0; kb < 2; kb++) {    // k-block of 32 halves = 4 chunks
            int rr = wc * 32 + nt * 8 + rin;
            int c  = kb * 4 + sel;
            b_off[nt][kb] = (u32)(rr * 128 + ((u32)(c ^ (rr & 7)) << 4));
        }

    // builder mapping: row iL = t>>3, 8 j's at jh
    const int iL = t >> 3;
    const int jt8 = t & 7;
    const int jh  = jt8 * 8;
    const u32 pst = (u32)(iL * 128 + (((u32)(jt8 ^ (iL & 7))) << 4));

    const float c1  = g_Ei[(size_t)b * Nn + i0 + iL];
    const float mE2 = g_maxE2[b];
    const float thrE = 1.0f / c1;
    // per-row power-of-2 scale: keep scaled max ~2^12
    float pm = c1 * mE2;
    pm = (pm >= 1.f) ? pm : pm * pm;
    int ex = (int)((__float_as_uint(pm) >> 23) & 255u) - 127;
    int kk = ex - 11; if (kk < 0) kk = 0;
    const float scale = __uint_as_float((u32)(127 - kk) << 23);
    const float c1s = c1 * scale;
    const float c2s = c1 * c1 * scale;

    const int*   arow = adj  + ((size_t)(b * Nn + i0 + iL)) * Nn + jh;
    const float* Ejb  = g_Ej + (size_t)b * Nn + jh;
    const __half* whtb = g_WhT + (size_t)b * FOUT * Nn;

    float acc[4][4];
    #pragma unroll
    for (int nt = 0; nt < 4; nt++)
        #pragma unroll
        for (int e = 0; e < 4; e++) acc[nt][e] = 0.f;

    int4   sav[2];
    float4 sev[2];
    float  rs = 0.f;

    #define ISSUE_G(c_) do {                                              \
        const int _j0 = (c_) * CH;                                        \
        sav[0] = *(const int4*)&arow[_j0];                                \
        sav[1] = *(const int4*)&arow[_j0 + 4];                            \
        sev[0] = *(const float4*)&Ejb[_j0];                               \
        sev[1] = *(const float4*)&Ejb[_j0 + 4];                           \
    } while (0)

    #define ISSUE_W(c_, buf_) do {                                        \
        const int _j0 = (c_) * CH;                                        \
        const u32 _wb = sb + SM_WS + (buf_) * 16384;                      \
        _Pragma("unroll")                                                 \
        for (int q = 0; q < 4; q++) {                                     \
            int flat = t + 256 * q;      /* 0..1023 16B chunks */         \
            int row  = flat >> 3;        /* f row */                      \
            int jc   = flat & 7;         /* chunk in row */               \
            u32 sidx = (u32)(row * 128 + (((u32)(jc ^ (row & 7))) << 4)); \
            CP_ASYNC16(_wb + sidx,                                        \
                       &whtb[(size_t)row * Nn + _j0 + jc * 8]);           \
        }                                                                  \
        CP_COMMIT();                                                       \
    } while (0)

    #define FINISH(buf_) do {                                              \
        const int*   _a = (const int*)sav;                                 \
        const float* _e = (const float*)sev;                               \
        uint4 pv; u32* pw = (u32*)&pv;                                     \
        _Pragma("unroll")                                                  \
        for (int u = 0; u < 4; u++) {                                      \
            float E0 = _e[u * 2], E1 = _e[u * 2 + 1];                      \
            float m0 = (E0 >= thrE) ? c1s : c2s * E0;                      \
            float m1 = (E1 >= thrE) ? c1s : c2s * E1;                      \
            float p0 = (_a[u * 2]     > 0) ? m0 * E0 : 0.f;                \
            float p1 = (_a[u * 2 + 1] > 0) ? m1 * E1 : 0.f;                \
            u32 h2 = pkh2(p0, p1);                                         \
            pw[u] = h2;                                                    \
            rs += __half2float(((const __half2*)&h2)->x)                   \
                + __half2float(((const __half2*)&h2)->y);                  \
        }                                                                   \
        *(uint4*)(dsm + SM_PS + (buf_) * 4096 + pst) = pv;                 \
    } while (0)

    // prologue: chunk 0
    ISSUE_W(0, 0);
    ISSUE_G(0);
    FINISH(0);
    CP_WAIT0();
    __syncthreads();

    for (int c = 0; c < NCH; c++) {
        const int s = c & 1;
        if (c < NCH - 1) { ISSUE_G(c + 1); ISSUE_W(c + 1, s ^ 1); }

        // MMA on buffer s
        {
            const u32 pb = sb + SM_PS + s * 4096;
            const u32 wb = sb + SM_WS + s * 16384;
            #pragma unroll
            for (int kb = 0; kb < 2; kb++) {
                u32 bfr[4][4];
                #pragma unroll
                for (int nt = 0; nt < 4; nt++)
                    ldmx4(bfr[nt], wb + b_off[nt][kb]);
                #pragma unroll
                for (int h = 0; h < 2; h++) {
                    u32 afr[4];
                    ldmx4(afr, pb + a_off[kb * 2 + h]);
                    #pragma unroll
                    for (int nt = 0; nt < 4; nt++)
                        mma16816(acc[nt], afr, &bfr[nt][h * 2]);
                }
            }
        }

        if (c < NCH - 1) FINISH(s ^ 1);
        CP_WAIT0();
        __syncthreads();
    }

    // rowsum: threads t..t|7 share builder row iL
    rs += __shfl_xor_sync(0xffffffffu, rs, 1);
    rs += __shfl_xor_sync(0xffffffffu, rs, 2);
    rs += __shfl_xor_sync(0xffffffffu, rs, 4);
    if ((t & 7) == 0) rows[iL] = rs;
    __syncthreads();

    // epilogue
    #pragma unroll
    for (int h = 0; h < 2; h++) {
        const int row = wr * 16 + g + h * 8;
        const float inv = 1.0f / rows[row];
        float* orow = out + ((size_t)(b * Nn + i0 + row)) * FOUT + wc * 32 + cl * 2;
        #pragma unroll
        for (int nt = 0; nt < 4; nt++) {
            float h0 = acc[nt][h * 2 + 0] * inv;
            float h1 = acc[nt][h * 2 + 1] * inv;
            h0 = (h0 > 0.f) ? h0 : expm1f(h0);
            h1 = (h1 > 0.f) ? h1 : expm1f(h1);
            float2 o = make_float2(h0, h1);
            *(float2*)&orow[nt * 8] = o;
        }
    }
}

// ============================================================
extern "C" void kernel_launch(void* const* d_in, const int* in_sizes, int n_in,
                              void* d_out, int out_size)
{
    const float* x   = (const float*)d_in[0];   // [8,2048,256] f32
    const int*   adj = (const int*)  d_in[1];   // [8,2048,2048] i32
    const float* W   = (const float*)d_in[2];   // [256,128] f32
    const float* a   = (const float*)d_in[3];   // [256,1] f32
    float*       out = (float*)d_out;           // [8,2048,128] f32

    dim3 g1(Nn / 64, Bb);
    gat_gemm_wh<<<g1, 256>>>(x, W, a);

    gat_maxe<<<Bb, 256>>>();

    dim3 g2(Nn / 32, Bb);
    gat_attn<<<g2, 256, SM_TOT>>>(adj, out);
}